// round 16
// baseline (speedup 1.0000x reference)
#include <cuda_runtime.h>
#include <cuda_bf16.h>
#include <math.h>
#include <cstdint>

// ---------------- problem constants ----------------
#define BATCH 512
#define SEQL  20
#define NNODE 16
#define EPS_  32
#define HDIM  128
#define VOCAB 100000
#define NTOT  (BATCH*NNODE)        // 8192
#define NEDGE (BATCH*EPS_)         // 16384
#define NOUT  (VOCAB-1)            // 99999
#define NT_   782                  // ceil(NOUT/128)
#define NPAD  (NT_*128)            // 100096 padded B rows
#define NJOBS (4*NT_)              // 3128
#define PGRID 148

// ---------------- device scratch (no allocs allowed) ----------------
__device__ float g_x[NTOT*HDIM];
__device__ float g_m[NTOT*HDIM];
__device__ float g_agg[NTOT*HDIM];
__device__ float g_gi[NTOT*3*HDIM];
__device__ float g_gh[NTOT*3*HDIM];
__device__ float g_gT[HDIM*HDIM];
__device__ float g_w1T[HDIM*HDIM];
__device__ float g_w2T[HDIM*HDIM];
__device__ float g_wtT[2*HDIM*HDIM];
// int8 fixed-point split of emb[1:] (padded) and afin
__device__ int8_t g_qbh[(size_t)NPAD*HDIM];
__device__ int8_t g_qbl[(size_t)NPAD*HDIM];
__device__ float  g_sb[NPAD];
__device__ int8_t g_qah[BATCH*HDIM];
__device__ int8_t g_qal[BATCH*HDIM];
__device__ float  g_sa[BATCH];

// ---------------- helpers ----------------
__device__ __forceinline__ uint32_t smem_to_u32(const void* p) {
    uint32_t a;
    asm("{ .reg .u64 t; cvta.to.shared.u64 t, %1; cvt.u32.u64 %0, t; }" : "=r"(a) : "l"(p));
    return a;
}

// bf16 split for the small GEMMs (unchanged, proven path)
__device__ __forceinline__ void split2(float x, float y, uint32_t& hi, uint32_t& lo) {
    uint32_t ux = __float_as_uint(x), uy = __float_as_uint(y);
    hi = __byte_perm(ux, uy, 0x7632);
    float lx = x - __uint_as_float(ux & 0xffff0000u);
    float ly = y - __uint_as_float(uy & 0xffff0000u);
    __nv_bfloat162 t = __floats2bfloat162_rn(lx, ly);
    lo = *reinterpret_cast<uint32_t*>(&t);
}

#define MMA_BF16(d, a, b)                                                        \
    asm volatile("mma.sync.aligned.m16n8k16.row.col.f32.bf16.bf16.f32 "         \
                 "{%0,%1,%2,%3}, {%4,%5,%6,%7}, {%8,%9}, {%0,%1,%2,%3};"        \
                 : "+f"((d)[0]), "+f"((d)[1]), "+f"((d)[2]), "+f"((d)[3])        \
                 : "r"((a)[0]), "r"((a)[1]), "r"((a)[2]), "r"((a)[3]),           \
                   "r"((b)[0]), "r"((b)[1]))

#define MMA_S8(d, a, b)                                                          \
    asm volatile("mma.sync.aligned.m16n8k32.row.col.s32.s8.s8.s32 "             \
                 "{%0,%1,%2,%3}, {%4,%5,%6,%7}, {%8,%9}, {%0,%1,%2,%3};"        \
                 : "+r"((d)[0]), "+r"((d)[1]), "+r"((d)[2]), "+r"((d)[3])        \
                 : "r"((a)[0]), "r"((a)[1]), "r"((a)[2]), "r"((a)[3]),           \
                   "r"((b)[0]), "r"((b)[1]))

#define CP_ASYNC16(daddr, gptr) \
    asm volatile("cp.async.cg.shared.global [%0], [%1], 16;" :: "r"(daddr), "l"(gptr))
#define CP_COMMIT() asm volatile("cp.async.commit_group;" ::: "memory")
#define CP_WAIT0()  asm volatile("cp.async.wait_group 0;"  ::: "memory")

// ================= small GEMMs: bf16 split path (r15, proven) =================
#define ROWB     272
#define TILE_B   34816
#define NTHR     512
#define SM_AHI   0
#define SM_ALO   34816
#define SM_BHI   69632
#define SM_BLO   104448
#define SM_TOTAL 139264

__device__ __forceinline__ void mma_compute(
    const char* aHb, const char* aLb, const char* bHb, const char* bLb,
    int wm, int wn, int g, int tig, float acc[2][4][4])
{
    const char* aH = aHb + (uint32_t)(wm * 32 + g) * ROWB + tig * 4;
    const char* aL = aLb + (uint32_t)(wm * 32 + g) * ROWB + tig * 4;
    const char* bH = bHb + (uint32_t)(wn * 32 + g) * ROWB + tig * 4;
    const char* bL = bLb + (uint32_t)(wn * 32 + g) * ROWB + tig * 4;

    #pragma unroll
    for (int ks = 0; ks < 8; ++ks) {
        const int kb = ks * 32;
        uint32_t ah[2][4], al[2][4], bh[4][2], bl[4][2];
        #pragma unroll
        for (int mf = 0; mf < 2; ++mf) {
            const char* p = aH + mf * (16 * ROWB) + kb;
            ah[mf][0] = *reinterpret_cast<const uint32_t*>(p);
            ah[mf][1] = *reinterpret_cast<const uint32_t*>(p + 8 * ROWB);
            ah[mf][2] = *reinterpret_cast<const uint32_t*>(p + 16);
            ah[mf][3] = *reinterpret_cast<const uint32_t*>(p + 8 * ROWB + 16);
            const char* q = aL + mf * (16 * ROWB) + kb;
            al[mf][0] = *reinterpret_cast<const uint32_t*>(q);
            al[mf][1] = *reinterpret_cast<const uint32_t*>(q + 8 * ROWB);
            al[mf][2] = *reinterpret_cast<const uint32_t*>(q + 16);
            al[mf][3] = *reinterpret_cast<const uint32_t*>(q + 8 * ROWB + 16);
        }
        #pragma unroll
        for (int nf = 0; nf < 4; ++nf) {
            const char* p = bH + nf * (8 * ROWB) + kb;
            bh[nf][0] = *reinterpret_cast<const uint32_t*>(p);
            bh[nf][1] = *reinterpret_cast<const uint32_t*>(p + 16);
            const char* q = bL + nf * (8 * ROWB) + kb;
            bl[nf][0] = *reinterpret_cast<const uint32_t*>(q);
            bl[nf][1] = *reinterpret_cast<const uint32_t*>(q + 16);
        }
        #pragma unroll
        for (int mf = 0; mf < 2; ++mf)
            #pragma unroll
            for (int nf = 0; nf < 4; ++nf) {
                MMA_BF16(acc[mf][nf], ah[mf], bh[nf]);
                MMA_BF16(acc[mf][nf], ah[mf], bl[nf]);
                MMA_BF16(acc[mf][nf], al[mf], bh[nf]);
            }
    }
}

__device__ __forceinline__ void gemm_tile_body(
    const float* __restrict__ A, const float* __restrict__ B,
    float* __restrict__ C, int N, int mBase, int nBase, char* sm)
{
    const int tid  = threadIdx.x, wid = tid >> 5, lane = tid & 31;
    const int g    = lane >> 2, tig = lane & 3;

    #pragma unroll
    for (int it = 0; it < 8; ++it) {
        int idx = tid + it * NTHR;
        int r = idx >> 5, c4 = (idx & 31) << 2;
        uint32_t soff = (uint32_t)r * ROWB + (uint32_t)c4 * 2;

        float4 v = *reinterpret_cast<const float4*>(A + (size_t)(mBase + r) * 128 + c4);
        uint32_t h0, l0, h1, l1;
        split2(v.x, v.y, h0, l0);
        split2(v.z, v.w, h1, l1);
        *reinterpret_cast<uint2*>(sm + SM_AHI + soff) = make_uint2(h0, h1);
        *reinterpret_cast<uint2*>(sm + SM_ALO + soff) = make_uint2(l0, l1);

        int n = nBase + r;
        float4 w = make_float4(0.f, 0.f, 0.f, 0.f);
        if (n < N) w = *reinterpret_cast<const float4*>(B + (size_t)n * 128 + c4);
        split2(w.x, w.y, h0, l0);
        split2(w.z, w.w, h1, l1);
        *reinterpret_cast<uint2*>(sm + SM_BHI + soff) = make_uint2(h0, h1);
        *reinterpret_cast<uint2*>(sm + SM_BLO + soff) = make_uint2(l0, l1);
    }
    __syncthreads();

    const int wm = wid >> 2, wn = wid & 3;
    float acc[2][4][4];
    #pragma unroll
    for (int mf = 0; mf < 2; ++mf)
        #pragma unroll
        for (int nf = 0; nf < 4; ++nf)
            #pragma unroll
            for (int e = 0; e < 4; ++e) acc[mf][nf][e] = 0.f;

    mma_compute(sm + SM_AHI, sm + SM_ALO, sm + SM_BHI, sm + SM_BLO,
                wm, wn, g, tig, acc);

    #pragma unroll
    for (int mf = 0; mf < 2; ++mf) {
        int row0 = mBase + wm * 32 + mf * 16 + g;
        #pragma unroll
        for (int nf = 0; nf < 4; ++nf) {
            int col = nBase + wn * 32 + nf * 8 + tig * 2;
            if (col < N) {
                *reinterpret_cast<float2*>(&C[(size_t)row0 * N + col]) =
                    make_float2(acc[mf][nf][0], acc[mf][nf][1]);
                *reinterpret_cast<float2*>(&C[(size_t)(row0 + 8) * N + col]) =
                    make_float2(acc[mf][nf][2], acc[mf][nf][3]);
            }
        }
    }
}

__global__ __launch_bounds__(NTHR) void gemm_tc(
    const float* __restrict__ A, const float* __restrict__ B,
    float* __restrict__ C, int N)
{
    extern __shared__ char sm[];
    gemm_tile_body(A, B, C, N, blockIdx.y << 7, blockIdx.x << 7, sm);
}

__global__ __launch_bounds__(NTHR) void gemm_gates(
    const float* __restrict__ Wih, const float* __restrict__ Whh)
{
    extern __shared__ char sm[];
    int sel = blockIdx.x / 3, nb = blockIdx.x % 3;
    const float* A = sel ? g_x : g_agg;
    const float* B = sel ? Whh : Wih;
    float*       C = sel ? g_gh : g_gi;
    gemm_tile_body(A, B, C, 3 * HDIM, blockIdx.y << 7, nb << 7, sm);
}

// ================= persistent vocab GEMM: int8 split (m16n8k32) =================
// int8 tile: 128 rows x 128 cols, pitch 144 -> bank(row,tig) = (4row+tig)%32
#define PI8      144
#define TQ       18432          // 128*144
#define A_SA     (2*TQ)         // A scales (128 floats) after qh/ql tiles
#define REG_SZ   (2*TQ + 512)   // 37376 per region (qh + ql + scales)
#define B0(p)    (REG_SZ + (p)*REG_SZ)
#define SM_I8    (3*REG_SZ)     // 112128

__device__ __forceinline__ void ld_tile_i8(
    const int8_t* __restrict__ qh, const int8_t* __restrict__ ql,
    const float* __restrict__ s, int row0, uint32_t base, int tid)
{
    #pragma unroll
    for (int it = 0; it < 2; ++it) {
        int idx = tid + it * NTHR;         // 1024 chunks of 16B per tile
        int r = idx >> 3, c = idx & 7;
        uint32_t off = (uint32_t)r * PI8 + c * 16;
        CP_ASYNC16(base + off,      qh + (size_t)(row0 + r) * 128 + c * 16);
        CP_ASYNC16(base + TQ + off, ql + (size_t)(row0 + r) * 128 + c * 16);
    }
    if (tid < 32) CP_ASYNC16(base + 2 * TQ + tid * 16, s + row0 + tid * 4);
}

// int8 MMA: warp tile 32x32; acc1 = hi*hi, acc2 = hi*lo + lo*hi
__device__ __forceinline__ void mma_i8(
    const char* aQ, const char* aL, const char* bQ, const char* bL,
    int wm, int wn, int g, int tig, int acc1[2][4][4], int acc2[2][4][4])
{
    const char* aH = aQ + (uint32_t)(wm * 32 + g) * PI8 + tig * 4;
    const char* aLp = aL + (uint32_t)(wm * 32 + g) * PI8 + tig * 4;
    const char* bH = bQ + (uint32_t)(wn * 32 + g) * PI8 + tig * 4;
    const char* bLp = bL + (uint32_t)(wn * 32 + g) * PI8 + tig * 4;

    #pragma unroll
    for (int ks = 0; ks < 4; ++ks) {
        const int kb = ks * 32;
        uint32_t ah[2][4], al[2][4];
        #pragma unroll
        for (int mf = 0; mf < 2; ++mf) {
            const char* p = aH + mf * (16 * PI8) + kb;
            ah[mf][0] = *reinterpret_cast<const uint32_t*>(p);
            ah[mf][1] = *reinterpret_cast<const uint32_t*>(p + 8 * PI8);
            ah[mf][2] = *reinterpret_cast<const uint32_t*>(p + 16);
            ah[mf][3] = *reinterpret_cast<const uint32_t*>(p + 8 * PI8 + 16);
            const char* q = aLp + mf * (16 * PI8) + kb;
            al[mf][0] = *reinterpret_cast<const uint32_t*>(q);
            al[mf][1] = *reinterpret_cast<const uint32_t*>(q + 8 * PI8);
            al[mf][2] = *reinterpret_cast<const uint32_t*>(q + 16);
            al[mf][3] = *reinterpret_cast<const uint32_t*>(q + 8 * PI8 + 16);
        }
        #pragma unroll
        for (int nf = 0; nf < 4; ++nf) {
            uint32_t bh[2], bl[2];
            const char* p = bH + nf * (8 * PI8) + kb;
            bh[0] = *reinterpret_cast<const uint32_t*>(p);
            bh[1] = *reinterpret_cast<const uint32_t*>(p + 16);
            const char* q = bLp + nf * (8 * PI8) + kb;
            bl[0] = *reinterpret_cast<const uint32_t*>(q);
            bl[1] = *reinterpret_cast<const uint32_t*>(q + 16);
            #pragma unroll
            for (int mf = 0; mf < 2; ++mf) {
                MMA_S8(acc1[mf][nf], ah[mf], bh);   // hi*hi
                MMA_S8(acc2[mf][nf], ah[mf], bl);   // hi*lo
                MMA_S8(acc2[mf][nf], al[mf], bh);   // lo*hi
            }
        }
    }
}

__global__ __launch_bounds__(NTHR) void gemm_scores(float* __restrict__ C)
{
    extern __shared__ char sm[];
    uint32_t smb = smem_to_u32(sm);
    const int tid = threadIdx.x, wid = tid >> 5, lane = tid & 31;
    const int g = lane >> 2, tig = lane & 3;
    const int wm = wid >> 2, wn = wid & 3;
    const float* saf = reinterpret_cast<const float*>(sm + A_SA);

    int m_cur = 0;                          // blockIdx.x < 148 < NT_
    ld_tile_i8(g_qah, g_qal, g_sa, 0, smb, tid);
    ld_tile_i8(g_qbh, g_qbl, g_sb, blockIdx.x << 7, smb + B0(0), tid);
    CP_COMMIT();
    int p = 0;

    for (int j = blockIdx.x; j < NJOBS; j += PGRID) {
        const int n = j - m_cur * NT_;

        // current buffers ready; barrier proves previous job fully done
        CP_WAIT0();
        __syncthreads();

        const int jn = j + PGRID;
        const bool havenext = jn < NJOBS;
        const int mn = havenext ? jn / NT_ : -1;

        if (havenext && mn == m_cur) {       // prefetch next B during MMA
            ld_tile_i8(g_qbh, g_qbl, g_sb, (jn - mn * NT_) << 7,
                       smb + B0(1 - p), tid);
            CP_COMMIT();
        }

        int acc1[2][4][4], acc2[2][4][4];
        #pragma unroll
        for (int mf = 0; mf < 2; ++mf)
            #pragma unroll
            for (int nf = 0; nf < 4; ++nf)
                #pragma unroll
                for (int e = 0; e < 4; ++e) { acc1[mf][nf][e] = 0; acc2[mf][nf][e] = 0; }

        mma_i8(sm, sm + TQ, sm + B0(p), sm + B0(p) + TQ, wm, wn, g, tig, acc1, acc2);

        // epilogue: out = s_a*s_b*(hh + (hl+lh)/256); scalar stores (NOUT odd)
        const float* sbf = reinterpret_cast<const float*>(sm + B0(p) + 2 * TQ);
        const int mB = m_cur << 7, nB = n << 7;
        #pragma unroll
        for (int mf = 0; mf < 2; ++mf) {
            int rl = wm * 32 + mf * 16 + g;
            float sa0 = saf[rl], sa1 = saf[rl + 8];
            size_t r0 = (size_t)(mB + rl) * NOUT, r1 = (size_t)(mB + rl + 8) * NOUT;
            #pragma unroll
            for (int nf = 0; nf < 4; ++nf) {
                int cl = wn * 32 + nf * 8 + tig * 2;
                int col = nB + cl;
                float sb0 = sbf[cl], sb1 = sbf[cl + 1];
                if (col < NOUT) {
                    C[r0 + col] = sa0 * sb0 *
                        ((float)acc1[mf][nf][0] + (float)acc2[mf][nf][0] * 0.00390625f);
                    C[r1 + col] = sa1 * sb0 *
                        ((float)acc1[mf][nf][2] + (float)acc2[mf][nf][2] * 0.00390625f);
                }
                if (col + 1 < NOUT) {
                    C[r0 + col + 1] = sa0 * sb1 *
                        ((float)acc1[mf][nf][1] + (float)acc2[mf][nf][1] * 0.00390625f);
                    C[r1 + col + 1] = sa1 * sb1 *
                        ((float)acc1[mf][nf][3] + (float)acc2[mf][nf][3] * 0.00390625f);
                }
            }
        }

        if (havenext && mn != m_cur) {       // rare m transition
            __syncthreads();                 // all reads of A (and saf) done
            m_cur = mn;
            ld_tile_i8(g_qah, g_qal, g_sa, m_cur << 7, smb, tid);
            ld_tile_i8(g_qbh, g_qbl, g_sb, (jn - mn * NT_) << 7,
                       smb + B0(1 - p), tid);
            CP_COMMIT();
        }
        p ^= 1;
    }
}

// ---------------- prep: zero agg, transposes, x gather ----------------
__global__ void prep_kernel(const int* __restrict__ items,
                            const float* __restrict__ emb,
                            const float* __restrict__ ggnn,
                            const float* __restrict__ W1,
                            const float* __restrict__ W2,
                            const float* __restrict__ Wt) {
    int i = blockIdx.x * 256 + threadIdx.x;
    if (i < NTOT * HDIM) {
        g_agg[i] = 0.f;
        int node = i >> 7, h = i & 127;
        g_x[i] = emb[(size_t)items[node] * 128 + h];
    }
    if (i < HDIM * HDIM) {
        int r = i >> 7, c = i & 127;
        g_gT[c * 128 + r]  = ggnn[i];
        g_w1T[c * 128 + r] = W1[i];
        g_w2T[c * 128 + r] = W2[i];
    }
    if (i < 2 * HDIM * HDIM) {
        int r = i >> 8, c = i & 255;
        g_wtT[c * 128 + r] = Wt[i];
    }
}

// ---------------- emb row quantization (one row per block) ----------------
__global__ __launch_bounds__(128) void quant_emb(const float* __restrict__ emb) {
    int n = blockIdx.x, h = threadIdx.x;
    __shared__ float red[4];
    float v = (n < NOUT) ? emb[(size_t)(n + 1) * 128 + h] : 0.f;
    float m = fabsf(v);
    #pragma unroll
    for (int o = 16; o > 0; o >>= 1) m = fmaxf(m, __shfl_xor_sync(0xffffffffu, m, o));
    if ((h & 31) == 0) red[h >> 5] = m;
    __syncthreads();
    m = fmaxf(fmaxf(red[0], red[1]), fmaxf(red[2], red[3]));

    float s   = m * (1.f / 127.f);
    float inv = (m > 0.f) ? 127.f / m : 0.f;
    float qh  = rintf(v * inv);
    float r   = v - qh * s;
    float ql  = fminf(127.f, fmaxf(-127.f, rintf(256.f * r * inv)));
    g_qbh[(size_t)n * 128 + h] = (int8_t)(int)qh;
    g_qbl[(size_t)n * 128 + h] = (int8_t)(int)ql;
    if (h == 0) g_sb[n] = s;
}

__global__ void scatter_kernel(const int* __restrict__ ei) {
    int i = blockIdx.x * 256 + threadIdx.x;
    int e = i >> 7, h = i & 127;
    int s = ei[e], d = ei[NEDGE + e];
    atomicAdd(&g_agg[(size_t)d * HDIM + h], g_m[(size_t)s * HDIM + h]);
}

// ---------------- fused GRU + hidden + attention + LN + quantize ----------------
__device__ __forceinline__ float blockSum128(float v, float* red) {
    #pragma unroll
    for (int o = 16; o > 0; o >>= 1) v += __shfl_xor_sync(0xffffffffu, v, o);
    if ((threadIdx.x & 31) == 0) red[threadIdx.x >> 5] = v;
    __syncthreads();
    v = red[0] + red[1] + red[2] + red[3];
    __syncthreads();
    return v;
}

__global__ __launch_bounds__(128) void attn_kernel(
    const int* __restrict__ items, const int* __restrict__ seq,
    const int* __restrict__ mask,  const float* __restrict__ emb,
    const float* __restrict__ bih, const float* __restrict__ bhh,
    const float* __restrict__ b1,  const float* __restrict__ b2,
    const float* __restrict__ w3,  const float* __restrict__ bt,
    const float* __restrict__ gamma, const float* __restrict__ beta)
{
    int b = blockIdx.x, h = threadIdx.x;
    __shared__ float xg[NNODE][HDIM];
    __shared__ float hid[SEQL][HDIM];
    __shared__ float a_s[HDIM], ht_s[HDIM];
    __shared__ float red[4];
    __shared__ int it_s[NNODE];
    __shared__ int msk[SEQL];
    __shared__ int sl;

    if (h < NNODE) it_s[h] = items[b * NNODE + h];
    if (h < SEQL)  msk[h]  = mask[b * SEQL + h];
    if (h == 0) {
        int c = 0;
        for (int l = 0; l < SEQL; ++l) c += mask[b * SEQL + l];
        sl = c - 1;
    }
    __syncthreads();

    float bi0 = bih[h], bi1 = bih[128 + h], bi2 = bih[256 + h];
    float bh0 = bhh[h], bh1 = bhh[128 + h], bh2 = bhh[256 + h];
    #pragma unroll 4
    for (int ni = 0; ni < NNODE; ++ni) {
        size_t node = (size_t)b * NNODE + ni;
        const float* gi = g_gi + node * 384;
        const float* gh = g_gh + node * 384;
        float r = 1.f / (1.f + expf(-((gi[h] + bi0) + (gh[h] + bh0))));
        float z = 1.f / (1.f + expf(-((gi[128 + h] + bi1) + (gh[128 + h] + bh1))));
        float nn = tanhf((gi[256 + h] + bi2) + r * (gh[256 + h] + bh2));
        float xo = g_x[node * HDIM + h];
        xg[ni][h] = (1.f - z) * nn + z * xo;
    }
    __syncthreads();

    for (int l = 0; l < SEQL; ++l) {
        int s = seq[b * SEQL + l];
        float v = 0.f;
        if (s != 0) {
            int found = -1;
            #pragma unroll
            for (int ni = 0; ni < NNODE; ++ni)
                if (found < 0 && it_s[ni] == s) found = ni;
            v = (found >= 0) ? xg[found][h] : emb[(size_t)s * HDIM + h];
        }
        hid[l][h] = v;
    }
    __syncthreads();
    ht_s[h] = hid[sl][h];
    __syncthreads();

    float q1v = b1[h];
    #pragma unroll 8
    for (int k = 0; k < HDIM; ++k) q1v += ht_s[k] * g_w1T[k * 128 + h];

    float w3v = w3[h];
    float acc = 0.f;
    for (int l = 0; l < SEQL; ++l) {
        float q2v = b2[h];
        #pragma unroll 8
        for (int k = 0; k < HDIM; ++k) q2v += hid[l][k] * g_w2T[k * 128 + h];
        float s = 1.f / (1.f + expf(-(q1v + q2v)));
        float alpha = blockSum128(s * w3v, red);
        if (msk[l]) acc += alpha * hid[l][h];
    }
    a_s[h] = acc;
    __syncthreads();

    float av = bt[h];
    #pragma unroll 8
    for (int k = 0; k < HDIM; ++k) av += a_s[k]  * g_wtT[k * 128 + h];
    #pragma unroll 8
    for (int k = 0; k < HDIM; ++k) av += ht_s[k] * g_wtT[(128 + k) * 128 + h];

    float mu  = blockSum128(av, red) * (1.f / HDIM);
    float d   = av - mu;
    float var = blockSum128(d * d, red) * (1.f / HDIM);
    float v   = d * rsqrtf(var + 1e-5f) * gamma[h] + beta[h];

    // quantize afin row (int8 fixed-point split)
    float m = fabsf(v);
    #pragma unroll
    for (int o = 16; o > 0; o >>= 1) m = fmaxf(m, __shfl_xor_sync(0xffffffffu, m, o));
    if ((h & 31) == 0) red[h >> 5] = m;
    __syncthreads();
    m = fmaxf(fmaxf(red[0], red[1]), fmaxf(red[2], red[3]));

    float s   = m * (1.f / 127.f);
    float inv = (m > 0.f) ? 127.f / m : 0.f;
    float qh  = rintf(v * inv);
    float r   = v - qh * s;
    float ql  = fminf(127.f, fmaxf(-127.f, rintf(256.f * r * inv)));
    g_qah[b * 128 + h] = (int8_t)(int)qh;
    g_qal[b * 128 + h] = (int8_t)(int)ql;
    if (h == 0) g_sa[b] = s;
}

// ---------------- launch ----------------
extern "C" void kernel_launch(void* const* d_in, const int* in_sizes, int n_in,
                              void* d_out, int out_size) {
    const int*   items = (const int*)  d_in[0];
    const int*   eidx  = (const int*)  d_in[1];
    const int*   seq   = (const int*)  d_in[2];
    const int*   mask  = (const int*)  d_in[3];
    const float* emb   = (const float*)d_in[4];
    const float* ggnn  = (const float*)d_in[5];
    const float* Wih   = (const float*)d_in[6];
    const float* Whh   = (const float*)d_in[7];
    const float* bih   = (const float*)d_in[8];
    const float* bhh   = (const float*)d_in[9];
    const float* W1    = (const float*)d_in[10];
    const float* b1    = (const float*)d_in[11];
    const float* W2    = (const float*)d_in[12];
    const float* b2    = (const float*)d_in[13];
    const float* w3    = (const float*)d_in[14];
    const float* Wt    = (const float*)d_in[15];
    const float* bt    = (const float*)d_in[16];
    const float* gamma = (const float*)d_in[17];
    const float* beta  = (const float*)d_in[18];
    float* out = (float*)d_out;

    float *px, *pgT, *pm;
    cudaGetSymbolAddress((void**)&px,  g_x);
    cudaGetSymbolAddress((void**)&pgT, g_gT);
    cudaGetSymbolAddress((void**)&pm,  g_m);

    cudaFuncSetAttribute(gemm_tc,     cudaFuncAttributeMaxDynamicSharedMemorySize, SM_TOTAL);
    cudaFuncSetAttribute(gemm_gates,  cudaFuncAttributeMaxDynamicSharedMemorySize, SM_TOTAL);
    cudaFuncSetAttribute(gemm_scores, cudaFuncAttributeMaxDynamicSharedMemorySize, SM_I8);

    prep_kernel<<<4096, 256>>>(items, emb, ggnn, W1, W2, Wt);             // 0
    quant_emb<<<NPAD, 128>>>(emb);                                        // 1
    gemm_tc<<<dim3(1, 64), NTHR, SM_TOTAL>>>(px, pgT, pm, HDIM);          // 2
    scatter_kernel<<<NEDGE/2, 256>>>(eidx);                               // 3
    gemm_gates<<<dim3(6, 64), NTHR, SM_TOTAL>>>(Wih, Whh);                // 4
    attn_kernel<<<BATCH, 128>>>(items, seq, mask, emb, bih, bhh,          // 5
                                b1, b2, w3, bt, gamma, beta);
    gemm_scores<<<PGRID, NTHR, SM_I8>>>(out);                             // 6
}